// round 6
// baseline (speedup 1.0000x reference)
#include <cuda_runtime.h>

typedef unsigned long long ull;

__device__ __forceinline__ ull ffma2(ull a, ull b, ull c) {
    ull d;
    asm("fma.rn.f32x2 %0, %1, %2, %3;" : "=l"(d) : "l"(a), "l"(b), "l"(c));
    return d;
}
__device__ __forceinline__ ull add2(ull a, ull b) {
    ull d;
    asm("add.rn.f32x2 %0, %1, %2;" : "=l"(d) : "l"(a), "l"(b));
    return d;
}
__device__ __forceinline__ ull bcast2(float x) {
    ull r; asm("mov.b64 %0, {%1, %1};" : "=l"(r) : "f"(x)); return r;
}
__device__ __forceinline__ ull pack2(float x, float y) {
    ull r; asm("mov.b64 %0, {%1, %2};" : "=l"(r) : "f"(x), "f"(y)); return r;
}
__device__ __forceinline__ float2 unpack2(ull v) {
    float2 r; asm("mov.b64 {%0, %1}, %2;" : "=f"(r.x), "=f"(r.y) : "l"(v)); return r;
}

// out = relu(f @ W1^T + b1) @ Wb^T + bb,  W1 = Wa@Wt, b1 = Wa@bt + ba.
// 4 lanes per point, each lane owns 4 output channels; weights register-resident
// (permuted per-lane gather order); f and h exchanged via SHFL.IDX; 4 accumulator
// chains per layer; DEPTH-2 software pipeline on the feature loads so DRAM
// latency is covered by ~2 full iterations of compute.
__global__ void __launch_bounds__(128, 3)
dmasif_shfl_kernel(const float4* __restrict__ feat4,
                   const float* __restrict__ Wt,
                   const float* __restrict__ bt,
                   const float* __restrict__ Wa,
                   const float* __restrict__ ba,
                   const float* __restrict__ Wb,
                   const float* __restrict__ bb,
                   float4* __restrict__ out4,
                   int n)
{
    __shared__ float sW1[16][16];   // fused Wa@Wt, [out][in]
    __shared__ float sWb[16][16];   // Wb, [out][in]
    __shared__ __align__(8) float sb1[16];
    __shared__ __align__(8) float sbb[16];

    const int t = threadIdx.x;
    #pragma unroll
    for (int e = t; e < 256; e += 128) {
        const int c = e >> 4, j = e & 15;
        float acc = 0.f;
        #pragma unroll
        for (int k = 0; k < 16; k++)
            acc = fmaf(Wa[c * 16 + k], Wt[k * 16 + j], acc);
        sW1[c][j] = acc;
        sWb[c][j] = Wb[c * 16 + j];
    }
    if (t < 16) {
        float acc = ba[t];
        #pragma unroll
        for (int k = 0; k < 16; k++)
            acc = fmaf(Wa[t * 16 + k], bt[k], acc);
        sb1[t] = acc;
        sbb[t] = bb[t];
    }
    __syncthreads();

    const int lane = t & 31;
    const int q = lane & 3;

    // Register weights, permuted to this lane's gather order:
    // step i visits input channel j = ((q + i/4)&3)*4 + i%4.
    ull w1a[16], w1b[16], wba[16], wbb[16];
    #pragma unroll
    for (int i = 0; i < 16; i++) {
        const int j = (((q + (i >> 2)) & 3) << 2) | (i & 3);
        w1a[i] = pack2(sW1[4 * q + 0][j], sW1[4 * q + 1][j]);
        w1b[i] = pack2(sW1[4 * q + 2][j], sW1[4 * q + 3][j]);
        wba[i] = pack2(sWb[4 * q + 0][j], sWb[4 * q + 1][j]);
        wbb[i] = pack2(sWb[4 * q + 2][j], sWb[4 * q + 3][j]);
    }
    // Biases come from shared each iteration (LDS.64); frees 8 registers for the
    // deeper pipeline. ptxas may hoist them back into regs if there is room.
    const ull* b1v = reinterpret_cast<const ull*>(&sb1[4 * q]);
    const ull* bbv = reinterpret_cast<const ull*>(&sbb[4 * q]);

    const unsigned FULL = 0xffffffffu;
    const int sg = lane & ~3;
    const int s1 = sg | ((q + 1) & 3);
    const int s2 = sg | ((q + 2) & 3);
    const int s3 = sg | ((q + 3) & 3);

    const int pid     = lane >> 2;                       // point slot 0..7
    const int gwarp   = (blockIdx.x * blockDim.x + t) >> 5;
    const int nwarps  = (gridDim.x * blockDim.x) >> 5;
    const int ngroups = (n + 7) >> 3;                    // 8 points per warp-iter
    if (gwarp >= ngroups) return;

    int g0 = gwarp;
    int g1 = g0 + nwarps;

    float4 f0 = make_float4(0.f, 0.f, 0.f, 0.f);
    float4 f1 = make_float4(0.f, 0.f, 0.f, 0.f);
    { const int p = g0 * 8 + pid; if (p < n) f0 = feat4[g0 * 32 + lane]; }
    if (g1 < ngroups) { const int p = g1 * 8 + pid; if (p < n) f1 = feat4[g1 * 32 + lane]; }

    for (;;) {
        // stage the load for two iterations ahead
        const int g2 = g1 + nwarps;
        float4 f2 = make_float4(0.f, 0.f, 0.f, 0.f);
        if (g2 < ngroups) {
            const int p = g2 * 8 + pid;
            if (p < n) f2 = feat4[g2 * 32 + lane];
        }

        // ================= compute on (g0, f0) =================
        // ---- layer 1: 4 independent chains
        ull c0 = b1v[0], c1 = b1v[1], c2 = 0ull, c3 = 0ull;

        const float g1x = __shfl_sync(FULL, f0.x, s1), g1y = __shfl_sync(FULL, f0.y, s1);
        const float g1z = __shfl_sync(FULL, f0.z, s1), g1w = __shfl_sync(FULL, f0.w, s1);
        const float g2x = __shfl_sync(FULL, f0.x, s2), g2y = __shfl_sync(FULL, f0.y, s2);
        const float g2z = __shfl_sync(FULL, f0.z, s2), g2w = __shfl_sync(FULL, f0.w, s2);
        const float g3x = __shfl_sync(FULL, f0.x, s3), g3y = __shfl_sync(FULL, f0.y, s3);
        const float g3z = __shfl_sync(FULL, f0.z, s3), g3w = __shfl_sync(FULL, f0.w, s3);

        {
            ull v;
            v = bcast2(f0.x); c0 = ffma2(v, w1a[0], c0);  c1 = ffma2(v, w1b[0], c1);
            v = bcast2(f0.y); c0 = ffma2(v, w1a[1], c0);  c1 = ffma2(v, w1b[1], c1);
            v = bcast2(f0.z); c0 = ffma2(v, w1a[2], c0);  c1 = ffma2(v, w1b[2], c1);
            v = bcast2(f0.w); c0 = ffma2(v, w1a[3], c0);  c1 = ffma2(v, w1b[3], c1);
            v = bcast2(g2x);  c2 = ffma2(v, w1a[8], c2);  c3 = ffma2(v, w1b[8], c3);
            v = bcast2(g2y);  c2 = ffma2(v, w1a[9], c2);  c3 = ffma2(v, w1b[9], c3);
            v = bcast2(g2z);  c2 = ffma2(v, w1a[10], c2); c3 = ffma2(v, w1b[10], c3);
            v = bcast2(g2w);  c2 = ffma2(v, w1a[11], c2); c3 = ffma2(v, w1b[11], c3);
            v = bcast2(g1x);  c0 = ffma2(v, w1a[4], c0);  c1 = ffma2(v, w1b[4], c1);
            v = bcast2(g1y);  c0 = ffma2(v, w1a[5], c0);  c1 = ffma2(v, w1b[5], c1);
            v = bcast2(g1z);  c0 = ffma2(v, w1a[6], c0);  c1 = ffma2(v, w1b[6], c1);
            v = bcast2(g1w);  c0 = ffma2(v, w1a[7], c0);  c1 = ffma2(v, w1b[7], c1);
            v = bcast2(g3x);  c2 = ffma2(v, w1a[12], c2); c3 = ffma2(v, w1b[12], c3);
            v = bcast2(g3y);  c2 = ffma2(v, w1a[13], c2); c3 = ffma2(v, w1b[13], c3);
            v = bcast2(g3z);  c2 = ffma2(v, w1a[14], c2); c3 = ffma2(v, w1b[14], c3);
            v = bcast2(g3w);  c2 = ffma2(v, w1a[15], c2); c3 = ffma2(v, w1b[15], c3);
        }
        const ull a0 = add2(c0, c2);
        const ull a1 = add2(c1, c3);

        // ---- ReLU: this lane owns h channels 4q..4q+3
        const float2 u0 = unpack2(a0), u1 = unpack2(a1);
        const float h0 = fmaxf(u0.x, 0.f), h1 = fmaxf(u0.y, 0.f);
        const float h2 = fmaxf(u1.x, 0.f), h3 = fmaxf(u1.y, 0.f);

        // ---- layer 2
        ull d0 = bbv[0], d1 = bbv[1], d2 = 0ull, d3 = 0ull;

        const float k1x = __shfl_sync(FULL, h0, s1), k1y = __shfl_sync(FULL, h1, s1);
        const float k1z = __shfl_sync(FULL, h2, s1), k1w = __shfl_sync(FULL, h3, s1);
        const float k2x = __shfl_sync(FULL, h0, s2), k2y = __shfl_sync(FULL, h1, s2);
        const float k2z = __shfl_sync(FULL, h2, s2), k2w = __shfl_sync(FULL, h3, s2);
        const float k3x = __shfl_sync(FULL, h0, s3), k3y = __shfl_sync(FULL, h1, s3);
        const float k3z = __shfl_sync(FULL, h2, s3), k3w = __shfl_sync(FULL, h3, s3);

        {
            ull v;
            v = bcast2(h0);  d0 = ffma2(v, wba[0], d0);  d1 = ffma2(v, wbb[0], d1);
            v = bcast2(h1);  d0 = ffma2(v, wba[1], d0);  d1 = ffma2(v, wbb[1], d1);
            v = bcast2(h2);  d0 = ffma2(v, wba[2], d0);  d1 = ffma2(v, wbb[2], d1);
            v = bcast2(h3);  d0 = ffma2(v, wba[3], d0);  d1 = ffma2(v, wbb[3], d1);
            v = bcast2(k2x); d2 = ffma2(v, wba[8], d2);  d3 = ffma2(v, wbb[8], d3);
            v = bcast2(k2y); d2 = ffma2(v, wba[9], d2);  d3 = ffma2(v, wbb[9], d3);
            v = bcast2(k2z); d2 = ffma2(v, wba[10], d2); d3 = ffma2(v, wbb[10], d3);
            v = bcast2(k2w); d2 = ffma2(v, wba[11], d2); d3 = ffma2(v, wbb[11], d3);
            v = bcast2(k1x); d0 = ffma2(v, wba[4], d0);  d1 = ffma2(v, wbb[4], d1);
            v = bcast2(k1y); d0 = ffma2(v, wba[5], d0);  d1 = ffma2(v, wbb[5], d1);
            v = bcast2(k1z); d0 = ffma2(v, wba[6], d0);  d1 = ffma2(v, wbb[6], d1);
            v = bcast2(k1w); d0 = ffma2(v, wba[7], d0);  d1 = ffma2(v, wbb[7], d1);
            v = bcast2(k3x); d2 = ffma2(v, wba[12], d2); d3 = ffma2(v, wbb[12], d3);
            v = bcast2(k3y); d2 = ffma2(v, wba[13], d2); d3 = ffma2(v, wbb[13], d3);
            v = bcast2(k3z); d2 = ffma2(v, wba[14], d2); d3 = ffma2(v, wbb[14], d3);
            v = bcast2(k3w); d2 = ffma2(v, wba[15], d2); d3 = ffma2(v, wbb[15], d3);
        }
        const ull r0 = add2(d0, d2);
        const ull r1 = add2(d1, d3);

        {
            const int p = g0 * 8 + pid;
            if (p < n) {
                const float2 o0 = unpack2(r0), o1 = unpack2(r1);
                out4[g0 * 32 + lane] = make_float4(o0.x, o0.y, o1.x, o1.y);
            }
        }
        // ================= end compute =================

        if (g1 >= ngroups) break;
        g0 = g1; f0 = f1;
        g1 = g2; f1 = f2;
    }
}

extern "C" void kernel_launch(void* const* d_in, const int* in_sizes, int n_in,
                              void* d_out, int out_size)
{
    // metadata order: features, points, nuv, Wt, bt, Wa, ba, Wb, bb, ranges
    const float4* feat = (const float4*)d_in[0];
    const float*  Wt   = (const float*)d_in[3];
    const float*  bt   = (const float*)d_in[4];
    const float*  Wa   = (const float*)d_in[5];
    const float*  ba   = (const float*)d_in[6];
    const float*  Wb   = (const float*)d_in[7];
    const float*  bb   = (const float*)d_in[8];
    float4* out = (float4*)d_out;

    const int n = in_sizes[0] / 16;   // number of points
    const int ngroups = (n + 7) / 8;
    int blocks = 148 * 3;             // exactly resident (3 CTAs/SM)
    const int maxBlocks = (ngroups * 32 + 127) / 128;
    if (blocks > maxBlocks) blocks = maxBlocks;
    if (blocks < 1) blocks = 1;
    dmasif_shfl_kernel<<<blocks, 128>>>(feat, Wt, bt, Wa, ba, Wb, bb, out, n);
}

// round 8
// speedup vs baseline: 1.5922x; 1.5922x over previous
#include <cuda_runtime.h>

typedef unsigned long long ull;

__device__ __forceinline__ ull ffma2(ull a, ull b, ull c) {
    ull d;
    asm("fma.rn.f32x2 %0, %1, %2, %3;" : "=l"(d) : "l"(a), "l"(b), "l"(c));
    return d;
}
__device__ __forceinline__ ull bcast2(float x) {
    ull r; asm("mov.b64 %0, {%1, %1};" : "=l"(r) : "f"(x)); return r;
}
__device__ __forceinline__ ull pack2(float x, float y) {
    ull r; asm("mov.b64 %0, {%1, %2};" : "=l"(r) : "f"(x), "f"(y)); return r;
}
__device__ __forceinline__ float2 unpack2(ull v) {
    float2 r; asm("mov.b64 {%0, %1}, %2;" : "=f"(r.x), "=f"(r.y) : "l"(v)); return r;
}

// Full per-group compute: f (this lane's float4 of the point) -> packed output
// pairs r0,r1. Weights/biases live in caller registers and are shared between
// the two interleaved groups.
__device__ __forceinline__ void compute_group(
    const float4 f,
    const ull* __restrict__ w1a, const ull* __restrict__ w1b,
    const ull* __restrict__ wba, const ull* __restrict__ wbb,
    ull b1p0, ull b1p1, ull bbp0, ull bbp1,
    int s1, int s2, int s3,
    ull& r0, ull& r1)
{
    const unsigned FULL = 0xffffffffu;

    // layer-1 exchange
    const float g1x = __shfl_sync(FULL, f.x, s1), g1y = __shfl_sync(FULL, f.y, s1);
    const float g1z = __shfl_sync(FULL, f.z, s1), g1w = __shfl_sync(FULL, f.w, s1);
    const float g2x = __shfl_sync(FULL, f.x, s2), g2y = __shfl_sync(FULL, f.y, s2);
    const float g2z = __shfl_sync(FULL, f.z, s2), g2w = __shfl_sync(FULL, f.w, s2);
    const float g3x = __shfl_sync(FULL, f.x, s3), g3y = __shfl_sync(FULL, f.y, s3);
    const float g3z = __shfl_sync(FULL, f.z, s3), g3w = __shfl_sync(FULL, f.w, s3);

    // layer 1: two chains (c0 -> channels 4q,4q+1 ; c1 -> 4q+2,4q+3)
    ull c0 = b1p0, c1 = b1p1, v;
    v = bcast2(f.x);  c0 = ffma2(v, w1a[0], c0);  c1 = ffma2(v, w1b[0], c1);
    v = bcast2(f.y);  c0 = ffma2(v, w1a[1], c0);  c1 = ffma2(v, w1b[1], c1);
    v = bcast2(f.z);  c0 = ffma2(v, w1a[2], c0);  c1 = ffma2(v, w1b[2], c1);
    v = bcast2(f.w);  c0 = ffma2(v, w1a[3], c0);  c1 = ffma2(v, w1b[3], c1);
    v = bcast2(g1x);  c0 = ffma2(v, w1a[4], c0);  c1 = ffma2(v, w1b[4], c1);
    v = bcast2(g1y);  c0 = ffma2(v, w1a[5], c0);  c1 = ffma2(v, w1b[5], c1);
    v = bcast2(g1z);  c0 = ffma2(v, w1a[6], c0);  c1 = ffma2(v, w1b[6], c1);
    v = bcast2(g1w);  c0 = ffma2(v, w1a[7], c0);  c1 = ffma2(v, w1b[7], c1);
    v = bcast2(g2x);  c0 = ffma2(v, w1a[8], c0);  c1 = ffma2(v, w1b[8], c1);
    v = bcast2(g2y);  c0 = ffma2(v, w1a[9], c0);  c1 = ffma2(v, w1b[9], c1);
    v = bcast2(g2z);  c0 = ffma2(v, w1a[10], c0); c1 = ffma2(v, w1b[10], c1);
    v = bcast2(g2w);  c0 = ffma2(v, w1a[11], c0); c1 = ffma2(v, w1b[11], c1);
    v = bcast2(g3x);  c0 = ffma2(v, w1a[12], c0); c1 = ffma2(v, w1b[12], c1);
    v = bcast2(g3y);  c0 = ffma2(v, w1a[13], c0); c1 = ffma2(v, w1b[13], c1);
    v = bcast2(g3z);  c0 = ffma2(v, w1a[14], c0); c1 = ffma2(v, w1b[14], c1);
    v = bcast2(g3w);  c0 = ffma2(v, w1a[15], c0); c1 = ffma2(v, w1b[15], c1);

    // ReLU
    const float2 u0 = unpack2(c0), u1 = unpack2(c1);
    const float h0 = fmaxf(u0.x, 0.f), h1 = fmaxf(u0.y, 0.f);
    const float h2 = fmaxf(u1.x, 0.f), h3 = fmaxf(u1.y, 0.f);

    // layer-2 exchange
    const float k1x = __shfl_sync(FULL, h0, s1), k1y = __shfl_sync(FULL, h1, s1);
    const float k1z = __shfl_sync(FULL, h2, s1), k1w = __shfl_sync(FULL, h3, s1);
    const float k2x = __shfl_sync(FULL, h0, s2), k2y = __shfl_sync(FULL, h1, s2);
    const float k2z = __shfl_sync(FULL, h2, s2), k2w = __shfl_sync(FULL, h3, s2);
    const float k3x = __shfl_sync(FULL, h0, s3), k3y = __shfl_sync(FULL, h1, s3);
    const float k3z = __shfl_sync(FULL, h2, s3), k3w = __shfl_sync(FULL, h3, s3);

    // layer 2
    ull d0 = bbp0, d1 = bbp1;
    v = bcast2(h0);   d0 = ffma2(v, wba[0], d0);  d1 = ffma2(v, wbb[0], d1);
    v = bcast2(h1);   d0 = ffma2(v, wba[1], d0);  d1 = ffma2(v, wbb[1], d1);
    v = bcast2(h2);   d0 = ffma2(v, wba[2], d0);  d1 = ffma2(v, wbb[2], d1);
    v = bcast2(h3);   d0 = ffma2(v, wba[3], d0);  d1 = ffma2(v, wbb[3], d1);
    v = bcast2(k1x);  d0 = ffma2(v, wba[4], d0);  d1 = ffma2(v, wbb[4], d1);
    v = bcast2(k1y);  d0 = ffma2(v, wba[5], d0);  d1 = ffma2(v, wbb[5], d1);
    v = bcast2(k1z);  d0 = ffma2(v, wba[6], d0);  d1 = ffma2(v, wbb[6], d1);
    v = bcast2(k1w);  d0 = ffma2(v, wba[7], d0);  d1 = ffma2(v, wbb[7], d1);
    v = bcast2(k2x);  d0 = ffma2(v, wba[8], d0);  d1 = ffma2(v, wbb[8], d1);
    v = bcast2(k2y);  d0 = ffma2(v, wba[9], d0);  d1 = ffma2(v, wbb[9], d1);
    v = bcast2(k2z);  d0 = ffma2(v, wba[10], d0); d1 = ffma2(v, wbb[10], d1);
    v = bcast2(k2w);  d0 = ffma2(v, wba[11], d0); d1 = ffma2(v, wbb[11], d1);
    v = bcast2(k3x);  d0 = ffma2(v, wba[12], d0); d1 = ffma2(v, wbb[12], d1);
    v = bcast2(k3y);  d0 = ffma2(v, wba[13], d0); d1 = ffma2(v, wbb[13], d1);
    v = bcast2(k3z);  d0 = ffma2(v, wba[14], d0); d1 = ffma2(v, wbb[14], d1);
    v = bcast2(k3w);  d0 = ffma2(v, wba[15], d0); d1 = ffma2(v, wbb[15], d1);

    r0 = d0; r1 = d1;
}

// out = relu(f @ W1^T + b1) @ Wb^T + bb,  W1 = Wa@Wt, b1 = Wa@bt + ba.
// 4 lanes per point, lane owns 4 output channels; weights register-resident and
// SHARED between TWO interleaved 8-point groups per iteration (16 independent
// dependence streams chip-wide at 8 warps/SM).
__global__ void __launch_bounds__(128, 2)
dmasif_shfl2_kernel(const float4* __restrict__ feat4,
                    const float* __restrict__ Wt,
                    const float* __restrict__ bt,
                    const float* __restrict__ Wa,
                    const float* __restrict__ ba,
                    const float* __restrict__ Wb,
                    const float* __restrict__ bb,
                    float4* __restrict__ out4,
                    int n)
{
    __shared__ float sW1[16][16];   // fused Wa@Wt, [out][in]
    __shared__ float sWb[16][16];   // Wb, [out][in]
    __shared__ float sb1[16];
    __shared__ float sbb[16];

    const int t = threadIdx.x;
    #pragma unroll
    for (int e = t; e < 256; e += 128) {
        const int c = e >> 4, j = e & 15;
        float acc = 0.f;
        #pragma unroll
        for (int k = 0; k < 16; k++)
            acc = fmaf(Wa[c * 16 + k], Wt[k * 16 + j], acc);
        sW1[c][j] = acc;
        sWb[c][j] = Wb[c * 16 + j];
    }
    if (t < 16) {
        float acc = ba[t];
        #pragma unroll
        for (int k = 0; k < 16; k++)
            acc = fmaf(Wa[t * 16 + k], bt[k], acc);
        sb1[t] = acc;
        sbb[t] = bb[t];
    }
    __syncthreads();

    const int lane = t & 31;
    const int q = lane & 3;

    // Register weights, permuted to this lane's gather order:
    // step i visits input channel j = ((q + i/4)&3)*4 + i%4.
    ull w1a[16], w1b[16], wba[16], wbb[16];
    #pragma unroll
    for (int i = 0; i < 16; i++) {
        const int j = (((q + (i >> 2)) & 3) << 2) | (i & 3);
        w1a[i] = pack2(sW1[4 * q + 0][j], sW1[4 * q + 1][j]);
        w1b[i] = pack2(sW1[4 * q + 2][j], sW1[4 * q + 3][j]);
        wba[i] = pack2(sWb[4 * q + 0][j], sWb[4 * q + 1][j]);
        wbb[i] = pack2(sWb[4 * q + 2][j], sWb[4 * q + 3][j]);
    }
    const ull b1p0 = pack2(sb1[4 * q + 0], sb1[4 * q + 1]);
    const ull b1p1 = pack2(sb1[4 * q + 2], sb1[4 * q + 3]);
    const ull bbp0 = pack2(sbb[4 * q + 0], sbb[4 * q + 1]);
    const ull bbp1 = pack2(sbb[4 * q + 2], sbb[4 * q + 3]);

    const int sg = lane & ~3;
    const int s1 = sg | ((q + 1) & 3);
    const int s2 = sg | ((q + 2) & 3);
    const int s3 = sg | ((q + 3) & 3);

    const int pid     = lane >> 2;                       // point slot 0..7
    const int gwarp   = (blockIdx.x * blockDim.x + t) >> 5;
    const int nwarps  = (gridDim.x * blockDim.x) >> 5;
    const int ngroups = (n + 7) >> 3;                    // 8 points / group
    const int stride  = 2 * nwarps;                      // 2 groups per iter
    if (gwarp >= ngroups) return;

    int gA = gwarp;
    int gB = gA + nwarps;

    float4 fA = make_float4(0.f, 0.f, 0.f, 0.f);
    float4 fB = make_float4(0.f, 0.f, 0.f, 0.f);
    { const int p = gA * 8 + pid; if (p < n) fA = feat4[gA * 32 + lane]; }
    if (gB < ngroups) { const int p = gB * 8 + pid; if (p < n) fB = feat4[gB * 32 + lane]; }

    for (;;) {
        // 1-deep prefetch for the next pair of groups
        const int nA = gA + stride;
        const int nB = gB + stride;
        float4 fnA = make_float4(0.f, 0.f, 0.f, 0.f);
        float4 fnB = make_float4(0.f, 0.f, 0.f, 0.f);
        if (nA < ngroups) { const int p = nA * 8 + pid; if (p < n) fnA = feat4[nA * 32 + lane]; }
        if (nB < ngroups) { const int p = nB * 8 + pid; if (p < n) fnB = feat4[nB * 32 + lane]; }

        // two independent streams; ptxas interleaves their chains
        ull rA0, rA1, rB0, rB1;
        compute_group(fA, w1a, w1b, wba, wbb, b1p0, b1p1, bbp0, bbp1, s1, s2, s3, rA0, rA1);
        compute_group(fB, w1a, w1b, wba, wbb, b1p0, b1p1, bbp0, bbp1, s1, s2, s3, rB0, rB1);

        {
            const int p = gA * 8 + pid;
            if (p < n) {
                const float2 o0 = unpack2(rA0), o1 = unpack2(rA1);
                out4[gA * 32 + lane] = make_float4(o0.x, o0.y, o1.x, o1.y);
            }
        }
        if (gB < ngroups) {
            const int p = gB * 8 + pid;
            if (p < n) {
                const float2 o0 = unpack2(rB0), o1 = unpack2(rB1);
                out4[gB * 32 + lane] = make_float4(o0.x, o0.y, o1.x, o1.y);
            }
        }

        if (nA >= ngroups) break;
        gA = nA; fA = fnA;
        gB = nB; fB = fnB;
    }
}

extern "C" void kernel_launch(void* const* d_in, const int* in_sizes, int n_in,
                              void* d_out, int out_size)
{
    // metadata order: features, points, nuv, Wt, bt, Wa, ba, Wb, bb, ranges
    const float4* feat = (const float4*)d_in[0];
    const float*  Wt   = (const float*)d_in[3];
    const float*  bt   = (const float*)d_in[4];
    const float*  Wa   = (const float*)d_in[5];
    const float*  ba   = (const float*)d_in[6];
    const float*  Wb   = (const float*)d_in[7];
    const float*  bb   = (const float*)d_in[8];
    float4* out = (float4*)d_out;

    const int n = in_sizes[0] / 16;   // number of points
    const int ngroups = (n + 7) / 8;
    int blocks = 148 * 2;             // exactly resident (2 CTAs/SM, 256-reg budget)
    const int maxBlocks = ((ngroups + 1) / 2 * 32 + 127) / 128;
    if (blocks > maxBlocks) blocks = maxBlocks;
    if (blocks < 1) blocks = 1;
    dmasif_shfl2_kernel<<<blocks, 128>>>(feat, Wt, bt, Wa, ba, Wb, bb, out, n);
}

// round 10
// speedup vs baseline: 1.8893x; 1.1866x over previous
#include <cuda_runtime.h>

typedef unsigned long long ull;

__device__ __forceinline__ ull ffma2(ull a, ull b, ull c) {
    ull d;
    asm("fma.rn.f32x2 %0, %1, %2, %3;" : "=l"(d) : "l"(a), "l"(b), "l"(c));
    return d;
}
__device__ __forceinline__ ull pack2(float x, float y) {
    ull r; asm("mov.b64 %0, {%1, %2};" : "=l"(r) : "f"(x), "f"(y)); return r;
}
__device__ __forceinline__ float hadd2(ull v) {
    float2 r; asm("mov.b64 {%0, %1}, %2;" : "=f"(r.x), "=f"(r.y) : "l"(v));
    return r.x + r.y;
}

// Per-group compute, pairwise-K packed: lane owns output channels 4q..4q+3.
// fp0 = (f[4q],f[4q+1]), fp1 = (f[4q+2],f[4q+3]) of this lane's point.
// Weight reg layout: w[cc*8+i] = (W[4q+cc][base], W[4q+cc][base+1]) with
// base = 4*((q + (i>>1))&3) + 2*(i&1)  — matches the exchange arrival order.
__device__ __forceinline__ void compute_group(
    ull fp0, ull fp1,
    const ull* __restrict__ w1, const ull* __restrict__ wb,
    ull b10, ull b11, ull b12, ull b13,
    ull bb0, ull bb1, ull bb2, ull bb3,
    int s1, int s2, int s3,
    float& o0, float& o1, float& o2, float& o3)
{
    const unsigned FULL = 0xffffffffu;

    // layer-1 exchange (64-bit shfls)
    const ull e10 = __shfl_sync(FULL, fp0, s1), e11 = __shfl_sync(FULL, fp1, s1);
    const ull e20 = __shfl_sync(FULL, fp0, s2), e21 = __shfl_sync(FULL, fp1, s2);
    const ull e30 = __shfl_sync(FULL, fp0, s3), e31 = __shfl_sync(FULL, fp1, s3);

    ull a0 = b10, a1 = b11, a2 = b12, a3 = b13;
#define L1STEP(vv, i) \
    a0 = ffma2(vv, w1[0*8+(i)], a0); a1 = ffma2(vv, w1[1*8+(i)], a1); \
    a2 = ffma2(vv, w1[2*8+(i)], a2); a3 = ffma2(vv, w1[3*8+(i)], a3);
    L1STEP(fp0, 0) L1STEP(fp1, 1)
    L1STEP(e10, 2) L1STEP(e11, 3)
    L1STEP(e20, 4) L1STEP(e21, 5)
    L1STEP(e30, 6) L1STEP(e31, 7)
#undef L1STEP

    // horizontal add + ReLU; repack as input pairs for layer 2
    const float h0 = fmaxf(hadd2(a0), 0.f);
    const float h1 = fmaxf(hadd2(a1), 0.f);
    const float h2 = fmaxf(hadd2(a2), 0.f);
    const float h3 = fmaxf(hadd2(a3), 0.f);
    const ull hp0 = pack2(h0, h1);
    const ull hp1 = pack2(h2, h3);

    // layer-2 exchange
    const ull k10 = __shfl_sync(FULL, hp0, s1), k11 = __shfl_sync(FULL, hp1, s1);
    const ull k20 = __shfl_sync(FULL, hp0, s2), k21 = __shfl_sync(FULL, hp1, s2);
    const ull k30 = __shfl_sync(FULL, hp0, s3), k31 = __shfl_sync(FULL, hp1, s3);

    ull d0 = bb0, d1 = bb1, d2 = bb2, d3 = bb3;
#define L2STEP(vv, i) \
    d0 = ffma2(vv, wb[0*8+(i)], d0); d1 = ffma2(vv, wb[1*8+(i)], d1); \
    d2 = ffma2(vv, wb[2*8+(i)], d2); d3 = ffma2(vv, wb[3*8+(i)], d3);
    L2STEP(hp0, 0) L2STEP(hp1, 1)
    L2STEP(k10, 2) L2STEP(k11, 3)
    L2STEP(k20, 4) L2STEP(k21, 5)
    L2STEP(k30, 6) L2STEP(k31, 7)
#undef L2STEP

    o0 = hadd2(d0); o1 = hadd2(d1); o2 = hadd2(d2); o3 = hadd2(d3);
}

// out = relu(f @ W1^T + b1) @ Wb^T + bb,  W1 = Wa@Wt, b1 = Wa@bt + ba.
// 4 lanes per point; weights register-resident, shared by THREE interleaved
// 8-point groups per iteration (24 independent streams per SM at 8 warps/SM).
__global__ void __launch_bounds__(128, 2)
dmasif_pk3_kernel(const ulonglong2* __restrict__ featu,
                  const float* __restrict__ Wt,
                  const float* __restrict__ bt,
                  const float* __restrict__ Wa,
                  const float* __restrict__ ba,
                  const float* __restrict__ Wb,
                  const float* __restrict__ bb,
                  float4* __restrict__ out4,
                  int n)
{
    __shared__ float sW1[16][16];   // fused Wa@Wt, [out][in]
    __shared__ float sWb[16][16];   // Wb, [out][in]
    __shared__ float sb1[16];
    __shared__ float sbb[16];

    const int t = threadIdx.x;
    #pragma unroll
    for (int e = t; e < 256; e += 128) {
        const int c = e >> 4, j = e & 15;
        float acc = 0.f;
        #pragma unroll
        for (int k = 0; k < 16; k++)
            acc = fmaf(Wa[c * 16 + k], Wt[k * 16 + j], acc);
        sW1[c][j] = acc;
        sWb[c][j] = Wb[c * 16 + j];
    }
    if (t < 16) {
        float acc = ba[t];
        #pragma unroll
        for (int k = 0; k < 16; k++)
            acc = fmaf(Wa[t * 16 + k], bt[k], acc);
        sb1[t] = acc;
        sbb[t] = bb[t];
    }
    __syncthreads();

    const int lane = t & 31;
    const int q = lane & 3;

    // Register weights, permuted to the pairwise gather arrival order.
    ull w1[32], wb[32];
    #pragma unroll
    for (int cc = 0; cc < 4; cc++) {
        const int c = 4 * q + cc;
        #pragma unroll
        for (int i = 0; i < 8; i++) {
            const int base = 4 * ((q + (i >> 1)) & 3) + 2 * (i & 1);
            w1[cc * 8 + i] = pack2(sW1[c][base], sW1[c][base + 1]);
            wb[cc * 8 + i] = pack2(sWb[c][base], sWb[c][base + 1]);
        }
    }
    const ull b10 = pack2(sb1[4*q+0], 0.f), b11 = pack2(sb1[4*q+1], 0.f);
    const ull b12 = pack2(sb1[4*q+2], 0.f), b13 = pack2(sb1[4*q+3], 0.f);
    const ull bb0 = pack2(sbb[4*q+0], 0.f), bb1 = pack2(sbb[4*q+1], 0.f);
    const ull bb2 = pack2(sbb[4*q+2], 0.f), bb3 = pack2(sbb[4*q+3], 0.f);

    const int sg = lane & ~3;
    const int s1 = sg | ((q + 1) & 3);
    const int s2 = sg | ((q + 2) & 3);
    const int s3 = sg | ((q + 3) & 3);

    const int pid     = lane >> 2;                       // point slot 0..7
    const int gwarp   = (blockIdx.x * blockDim.x + t) >> 5;
    const int nwarps  = (gridDim.x * blockDim.x) >> 5;
    const int ngroups = (n + 7) >> 3;                    // 8 points / group
    const int stride  = 3 * nwarps;                      // 3 groups per iter
    if (gwarp >= ngroups) return;

    int gA = gwarp, gB = gA + nwarps, gC = gB + nwarps;

    ulonglong2 fA = {0ull, 0ull}, fB = {0ull, 0ull}, fC = {0ull, 0ull};
    { const int p = gA * 8 + pid; if (p < n) fA = featu[gA * 32 + lane]; }
    if (gB < ngroups) { const int p = gB * 8 + pid; if (p < n) fB = featu[gB * 32 + lane]; }
    if (gC < ngroups) { const int p = gC * 8 + pid; if (p < n) fC = featu[gC * 32 + lane]; }

    for (;;) {
        const int nA = gA + stride, nB = gB + stride, nC = gC + stride;
        ulonglong2 fnA = {0ull, 0ull}, fnB = {0ull, 0ull}, fnC = {0ull, 0ull};
        if (nA < ngroups) { const int p = nA * 8 + pid; if (p < n) fnA = featu[nA * 32 + lane]; }
        if (nB < ngroups) { const int p = nB * 8 + pid; if (p < n) fnB = featu[nB * 32 + lane]; }
        if (nC < ngroups) { const int p = nC * 8 + pid; if (p < n) fnC = featu[nC * 32 + lane]; }

        float a0, a1, a2, a3, c0, c1, c2, c3, e0, e1, e2, e3;
        compute_group(fA.x, fA.y, w1, wb, b10, b11, b12, b13, bb0, bb1, bb2, bb3,
                      s1, s2, s3, a0, a1, a2, a3);
        compute_group(fB.x, fB.y, w1, wb, b10, b11, b12, b13, bb0, bb1, bb2, bb3,
                      s1, s2, s3, c0, c1, c2, c3);
        compute_group(fC.x, fC.y, w1, wb, b10, b11, b12, b13, bb0, bb1, bb2, bb3,
                      s1, s2, s3, e0, e1, e2, e3);

        { const int p = gA * 8 + pid;
          if (p < n) out4[gA * 32 + lane] = make_float4(a0, a1, a2, a3); }
        if (gB < ngroups) {
            const int p = gB * 8 + pid;
            if (p < n) out4[gB * 32 + lane] = make_float4(c0, c1, c2, c3);
        }
        if (gC < ngroups) {
            const int p = gC * 8 + pid;
            if (p < n) out4[gC * 32 + lane] = make_float4(e0, e1, e2, e3);
        }

        if (nA >= ngroups) break;
        gA = nA; fA = fnA;
        gB = nB; fB = fnB;
        gC = nC; fC = fnC;
    }
}

extern "C" void kernel_launch(void* const* d_in, const int* in_sizes, int n_in,
                              void* d_out, int out_size)
{
    // metadata order: features, points, nuv, Wt, bt, Wa, ba, Wb, bb, ranges
    const ulonglong2* feat = (const ulonglong2*)d_in[0];
    const float*  Wt   = (const float*)d_in[3];
    const float*  bt   = (const float*)d_in[4];
    const float*  Wa   = (const float*)d_in[5];
    const float*  ba   = (const float*)d_in[6];
    const float*  Wb   = (const float*)d_in[7];
    const float*  bb   = (const float*)d_in[8];
    float4* out = (float4*)d_out;

    const int n = in_sizes[0] / 16;   // number of points
    const int ngroups = (n + 7) / 8;
    int blocks = 148 * 2;             // exactly resident (2 CTAs/SM)
    const int maxBlocks = (ngroups + 3) / 4;   // >= 1 group per warp
    if (blocks > maxBlocks) blocks = maxBlocks;
    if (blocks < 1) blocks = 1;
    dmasif_pk3_kernel<<<blocks, 128>>>(feat, Wt, bt, Wa, ba, Wb, bb, out, n);
}